// round 2
// baseline (speedup 1.0000x reference)
#include <cuda_runtime.h>

#define NN 50000
#define NE 800000
#define F 64
#define KF 256    // F * K
#define OUTF 256

// Scratch (device globals: allocation-free rule)
__device__ __align__(16) float g_deg[NN];
__device__ __align__(16) float g_dsqrt[NN];
__device__ __align__(16) float g_scaled[NN * F];
__device__ __align__(16) float g_agg[NN * F];
__device__ __align__(16) float g_Xt[(size_t)NN * KF];

__global__ void k_zero() {
    int i = blockIdx.x * blockDim.x + threadIdx.x;
    if (i < NN * F) g_agg[i] = 0.f;
    if (i < NN) g_deg[i] = 0.f;
}

__global__ void k_deg(const int* __restrict__ dst) {
    int e = blockIdx.x * blockDim.x + threadIdx.x;
    if (e < NE) atomicAdd(&g_deg[dst[e]], 1.0f);
}

// One thread per (node, 4-float chunk): 16 chunks per node.
__global__ void k_prep(const float* __restrict__ x) {
    int t = blockIdx.x * blockDim.x + threadIdx.x;
    if (t >= NN * 16) return;
    int i = t >> 4, c = t & 15;
    float ds = rsqrtf(fmaxf(g_deg[i], 1.0f));
    if (c == 0) g_dsqrt[i] = ds;
    float4 v = ((const float4*)x)[(size_t)i * 16 + c];
    ((float4*)(g_Xt + (size_t)i * KF))[c] = v;   // X0 into block 0
    float4 s = make_float4(v.x * ds, v.y * ds, v.z * ds, v.w * ds);
    ((float4*)g_scaled)[(size_t)i * 16 + c] = s;
}

// One thread per (edge, 4-float chunk). Vector reduction to L2.
__global__ void k_scatter(const int* __restrict__ src, const int* __restrict__ dst) {
    int t = blockIdx.x * blockDim.x + threadIdx.x;
    if (t >= NE * 16) return;
    int e = t >> 4, c = t & 15;
    int s = __ldg(&src[e]);
    int d = __ldg(&dst[e]);
    float4 v = ((const float4*)g_scaled)[(size_t)s * 16 + c];
    float* p = g_agg + (size_t)d * F + c * 4;
    asm volatile("red.global.add.v4.f32 [%0], {%1,%2,%3,%4};"
                 :: "l"(p), "f"(v.x), "f"(v.y), "f"(v.z), "f"(v.w) : "memory");
}

// Finish Laplacian, apply Chebyshev recurrence, produce next scaled input,
// and re-zero agg for the next scatter (keeps scratch deterministic).
__global__ void k_finalize(const float* __restrict__ lambda_max, int step) {
    int t = blockIdx.x * blockDim.x + threadIdx.x;
    if (t >= NN * 16) return;
    int i = t >> 4, c = t & 15;
    float ds = g_dsqrt[i];
    float4* aggp = (float4*)g_agg + (size_t)i * 16 + c;
    float4 a = *aggp;
    *aggp = make_float4(0.f, 0.f, 0.f, 0.f);
    float rn = 2.0f / lambda_max[0];
    float4 L = make_float4(a.x * ds, a.y * ds, a.z * ds, a.w * ds);
    float4* XtRow = (float4*)(g_Xt + (size_t)i * KF);
    float4 xp = XtRow[(step - 1) * 16 + c];
    float4 xn;
    if (step == 1) {
        float cL = -rn, cP = rn - 1.0f;
        xn = make_float4(cL * L.x + cP * xp.x, cL * L.y + cP * xp.y,
                         cL * L.z + cP * xp.z, cL * L.w + cP * xp.w);
    } else {
        float4 xpp = XtRow[(step - 2) * 16 + c];
        float cL = -2.0f * rn, cP = 2.0f * (rn - 1.0f);
        xn = make_float4(cL * L.x + cP * xp.x - xpp.x, cL * L.y + cP * xp.y - xpp.y,
                         cL * L.z + cP * xp.z - xpp.z, cL * L.w + cP * xp.w - xpp.w);
    }
    XtRow[step * 16 + c] = xn;
    float4 s = make_float4(xn.x * ds, xn.y * ds, xn.z * ds, xn.w * ds);
    ((float4*)g_scaled)[(size_t)i * 16 + c] = s;
}

// C[M=50000, 256] = relu(Xt @ W + b). 64x64 tile, 256 threads, 4x4 per thread.
__global__ void k_gemm(const float* __restrict__ W, const float* __restrict__ bias,
                       float* __restrict__ out) {
    __shared__ float As[16][64];
    __shared__ float Bs[16][68];   // pad to dodge conflicts
    int m0 = blockIdx.y * 64, n0 = blockIdx.x * 64;
    int tid = threadIdx.x;
    int tx = tid & 15, ty = tid >> 4;
    float acc[4][4] = {};

    for (int kk = 0; kk < KF; kk += 16) {
        {
            int k = tid & 15, m = tid >> 4;
            #pragma unroll
            for (int r = 0; r < 4; r++) {
                int mm = m + r * 16;
                int row = m0 + mm;
                As[k][mm] = (row < NN) ? g_Xt[(size_t)row * KF + kk + k] : 0.f;
            }
        }
        {
            int n = tid & 63, k = tid >> 6;
            #pragma unroll
            for (int r = 0; r < 4; r++)
                Bs[k + r * 4][n] = W[(size_t)(kk + k + r * 4) * OUTF + n0 + n];
        }
        __syncthreads();
        #pragma unroll
        for (int k = 0; k < 16; k++) {
            float a[4], bb[4];
            #pragma unroll
            for (int i = 0; i < 4; i++) a[i] = As[k][ty * 4 + i];
            #pragma unroll
            for (int j = 0; j < 4; j++) bb[j] = Bs[k][tx * 4 + j];
            #pragma unroll
            for (int i = 0; i < 4; i++)
                #pragma unroll
                for (int j = 0; j < 4; j++)
                    acc[i][j] += a[i] * bb[j];
        }
        __syncthreads();
    }

    #pragma unroll
    for (int i = 0; i < 4; i++) {
        int row = m0 + ty * 4 + i;
        if (row >= NN) continue;
        #pragma unroll
        for (int j = 0; j < 4; j++) {
            int col = n0 + tx * 4 + j;
            float v = acc[i][j] + bias[col];
            out[(size_t)row * OUTF + col] = fmaxf(v, 0.f);
        }
    }
}

extern "C" void kernel_launch(void* const* d_in, const int* in_sizes, int n_in,
                              void* d_out, int out_size) {
    const float* signal = (const float*)d_in[0];
    const int*   src    = (const int*)d_in[1];
    const int*   dst    = (const int*)d_in[2];
    const float* lam    = (const float*)d_in[3];
    const float* W      = (const float*)d_in[4];
    const float* bias   = (const float*)d_in[5];
    float* out = (float*)d_out;

    k_zero<<<(NN * F + 255) / 256, 256>>>();
    k_deg<<<(NE + 255) / 256, 256>>>(dst);
    k_prep<<<(NN * 16 + 255) / 256, 256>>>(signal);

    for (int step = 1; step <= 3; step++) {
        k_scatter<<<(NE * 16 + 255) / 256, 256>>>(src, dst);
        k_finalize<<<(NN * 16 + 255) / 256, 256>>>(lam, step);
    }

    k_gemm<<<dim3(OUTF / 64, (NN + 63) / 64), 256>>>(W, bias, out);
}

// round 3
// speedup vs baseline: 1.6422x; 1.6422x over previous
#include <cuda_runtime.h>
#include <cstdint>

#define NN 50000
#define NE 800000
#define F 64
#define KF 256    // F * K
#define OUTF 256

// Scratch (device globals: allocation-free rule)
__device__ __align__(16) float g_deg[NN];
__device__ __align__(16) float g_dsqrt[NN];
__device__ __align__(16) float g_scaled[NN * F];
__device__ __align__(16) float g_agg[NN * F];
__device__ __align__(16) float g_Xt[(size_t)NN * KF];

__global__ void k_zero() {
    int i = blockIdx.x * blockDim.x + threadIdx.x;
    if (i < NN * F) g_agg[i] = 0.f;
    if (i < NN) g_deg[i] = 0.f;
}

__global__ void k_deg(const int* __restrict__ dst) {
    int e = blockIdx.x * blockDim.x + threadIdx.x;
    if (e < NE) atomicAdd(&g_deg[dst[e]], 1.0f);
}

// One thread per (node, 4-float chunk): 16 chunks per node.
__global__ void k_prep(const float* __restrict__ x) {
    int t = blockIdx.x * blockDim.x + threadIdx.x;
    if (t >= NN * 16) return;
    int i = t >> 4, c = t & 15;
    float ds = rsqrtf(fmaxf(g_deg[i], 1.0f));
    if (c == 0) g_dsqrt[i] = ds;
    float4 v = ((const float4*)x)[(size_t)i * 16 + c];
    ((float4*)(g_Xt + (size_t)i * KF))[c] = v;   // X0 into block 0
    float4 s = make_float4(v.x * ds, v.y * ds, v.z * ds, v.w * ds);
    ((float4*)g_scaled)[(size_t)i * 16 + c] = s;
}

// One thread per (edge, 4-float chunk). Vector reduction to L2.
__global__ void k_scatter(const int* __restrict__ src, const int* __restrict__ dst) {
    int t = blockIdx.x * blockDim.x + threadIdx.x;
    if (t >= NE * 16) return;
    int e = t >> 4, c = t & 15;
    int s = __ldg(&src[e]);
    int d = __ldg(&dst[e]);
    float4 v = ((const float4*)g_scaled)[(size_t)s * 16 + c];
    float* p = g_agg + (size_t)d * F + c * 4;
    asm volatile("red.global.add.v4.f32 [%0], {%1,%2,%3,%4};"
                 :: "l"(p), "f"(v.x), "f"(v.y), "f"(v.z), "f"(v.w) : "memory");
}

// Finish Laplacian, Chebyshev recurrence, produce next scaled input, re-zero agg.
__global__ void k_finalize(const float* __restrict__ lambda_max, int step) {
    int t = blockIdx.x * blockDim.x + threadIdx.x;
    if (t >= NN * 16) return;
    int i = t >> 4, c = t & 15;
    float ds = g_dsqrt[i];
    float4* aggp = (float4*)g_agg + (size_t)i * 16 + c;
    float4 a = *aggp;
    *aggp = make_float4(0.f, 0.f, 0.f, 0.f);
    float rn = 2.0f / lambda_max[0];
    float4 L = make_float4(a.x * ds, a.y * ds, a.z * ds, a.w * ds);
    float4* XtRow = (float4*)(g_Xt + (size_t)i * KF);
    float4 xp = XtRow[(step - 1) * 16 + c];
    float4 xn;
    if (step == 1) {
        float cL = -rn, cP = rn - 1.0f;
        xn = make_float4(cL * L.x + cP * xp.x, cL * L.y + cP * xp.y,
                         cL * L.z + cP * xp.z, cL * L.w + cP * xp.w);
    } else {
        float4 xpp = XtRow[(step - 2) * 16 + c];
        float cL = -2.0f * rn, cP = 2.0f * (rn - 1.0f);
        xn = make_float4(cL * L.x + cP * xp.x - xpp.x, cL * L.y + cP * xp.y - xpp.y,
                         cL * L.z + cP * xp.z - xpp.z, cL * L.w + cP * xp.w - xpp.w);
    }
    XtRow[step * 16 + c] = xn;
    float4 s = make_float4(xn.x * ds, xn.y * ds, xn.z * ds, xn.w * ds);
    ((float4*)g_scaled)[(size_t)i * 16 + c] = s;
}

// ---------------------------------------------------------------------------
// TF32 tensor-core GEMM: out[50000,256] = relu(Xt[50000,256] @ W[256,256] + b)
// 128x128 block tile, BK=32, 256 threads (8 warps, 4x2), warp tile 32x64,
// mma.sync.m16n8k8.tf32. Smem pitch 36 (== 4 mod 32) => conflict-free frags.
// ---------------------------------------------------------------------------
#define PITCH 36

__device__ __forceinline__ uint32_t f2tf32(float x) {
    uint32_t u;
    asm("cvt.rna.tf32.f32 %0, %1;" : "=r"(u) : "f"(x));
    return u;
}

__global__ __launch_bounds__(256) void k_gemm_tc(const float* __restrict__ W,
                                                 const float* __restrict__ bias,
                                                 float* __restrict__ out) {
    __shared__ uint32_t As[128 * PITCH];
    __shared__ uint32_t Bs[128 * PITCH];   // transposed: Bs[n][k]

    const int tid  = threadIdx.x;
    const int lane = tid & 31;
    const int warp = tid >> 5;
    const int warp_m = warp & 3;   // 0..3  -> 32-row slab
    const int warp_n = warp >> 2;  // 0..1  -> 64-col slab
    const int g = lane >> 2;       // groupID 0..7
    const int t = lane & 3;        // thread-in-group 0..3

    const int m0 = blockIdx.y * 128;
    const int n0 = blockIdx.x * 128;

    const int arow  = tid >> 1;          // 0..127
    const int ahalf = (tid & 1) * 16;    // 0 or 16 within BK
    const int brow  = tid >> 1;          // n index 0..127
    const int khalf = (tid & 1) * 16;

    float c[2][8][4];
    #pragma unroll
    for (int i = 0; i < 2; i++)
        #pragma unroll
        for (int j = 0; j < 8; j++)
            #pragma unroll
            for (int r = 0; r < 4; r++) c[i][j][r] = 0.f;

    const bool arow_ok = (m0 + arow) < NN;
    const float* gA = g_Xt + (size_t)(m0 + arow) * KF + ahalf;

    for (int kk = 0; kk < KF; kk += 32) {
        // ---- load A tile (with bounds + tf32 convert) ----
        #pragma unroll
        for (int j = 0; j < 4; j++) {
            float4 v = arow_ok ? *(const float4*)(gA + kk + j * 4)
                               : make_float4(0.f, 0.f, 0.f, 0.f);
            uint32_t* p = &As[arow * PITCH + ahalf + j * 4];
            p[0] = f2tf32(v.x); p[1] = f2tf32(v.y);
            p[2] = f2tf32(v.z); p[3] = f2tf32(v.w);
        }
        // ---- load B tile transposed (Bs[n][k]) ----
        #pragma unroll
        for (int j = 0; j < 16; j++) {
            float w = W[(size_t)(kk + khalf + j) * OUTF + n0 + brow];
            Bs[brow * PITCH + khalf + j] = f2tf32(w);
        }
        __syncthreads();

        #pragma unroll
        for (int kt = 0; kt < 4; kt++) {
            const int k0 = kt * 8;
            uint32_t a[2][4], b[8][2];
            #pragma unroll
            for (int mt = 0; mt < 2; mt++) {
                int base = warp_m * 32 + mt * 16;
                a[mt][0] = As[(base + g) * PITCH + k0 + t];
                a[mt][1] = As[(base + g + 8) * PITCH + k0 + t];
                a[mt][2] = As[(base + g) * PITCH + k0 + t + 4];
                a[mt][3] = As[(base + g + 8) * PITCH + k0 + t + 4];
            }
            #pragma unroll
            for (int nt = 0; nt < 8; nt++) {
                int nb = warp_n * 64 + nt * 8;
                b[nt][0] = Bs[(nb + g) * PITCH + k0 + t];
                b[nt][1] = Bs[(nb + g) * PITCH + k0 + t + 4];
            }
            #pragma unroll
            for (int mt = 0; mt < 2; mt++)
                #pragma unroll
                for (int nt = 0; nt < 8; nt++) {
                    asm volatile(
                        "mma.sync.aligned.m16n8k8.row.col.f32.tf32.tf32.f32 "
                        "{%0,%1,%2,%3}, {%4,%5,%6,%7}, {%8,%9}, {%0,%1,%2,%3};"
                        : "+f"(c[mt][nt][0]), "+f"(c[mt][nt][1]),
                          "+f"(c[mt][nt][2]), "+f"(c[mt][nt][3])
                        : "r"(a[mt][0]), "r"(a[mt][1]), "r"(a[mt][2]), "r"(a[mt][3]),
                          "r"(b[nt][0]), "r"(b[nt][1]));
                }
        }
        __syncthreads();
    }

    // ---- epilogue: bias + relu ----
    #pragma unroll
    for (int nt = 0; nt < 8; nt++) {
        int col = n0 + warp_n * 64 + nt * 8 + 2 * t;
        float bx = bias[col], by = bias[col + 1];
        #pragma unroll
        for (int mt = 0; mt < 2; mt++) {
            int r0 = m0 + warp_m * 32 + mt * 16 + g;
            if (r0 < NN) {
                float2 v = make_float2(fmaxf(c[mt][nt][0] + bx, 0.f),
                                       fmaxf(c[mt][nt][1] + by, 0.f));
                *(float2*)(out + (size_t)r0 * OUTF + col) = v;
            }
            int r1 = r0 + 8;
            if (r1 < NN) {
                float2 v = make_float2(fmaxf(c[mt][nt][2] + bx, 0.f),
                                       fmaxf(c[mt][nt][3] + by, 0.f));
                *(float2*)(out + (size_t)r1 * OUTF + col) = v;
            }
        }
    }
}

extern "C" void kernel_launch(void* const* d_in, const int* in_sizes, int n_in,
                              void* d_out, int out_size) {
    const float* signal = (const float*)d_in[0];
    const int*   src    = (const int*)d_in[1];
    const int*   dst    = (const int*)d_in[2];
    const float* lam    = (const float*)d_in[3];
    const float* W      = (const float*)d_in[4];
    const float* bias   = (const float*)d_in[5];
    float* out = (float*)d_out;

    k_zero<<<(NN * F + 255) / 256, 256>>>();
    k_deg<<<(NE + 255) / 256, 256>>>(dst);
    k_prep<<<(NN * 16 + 255) / 256, 256>>>(signal);

    for (int step = 1; step <= 3; step++) {
        k_scatter<<<(NE * 16 + 255) / 256, 256>>>(src, dst);
        k_finalize<<<(NN * 16 + 255) / 256, 256>>>(lam, step);
    }

    k_gemm_tc<<<dim3(OUTF / 128, (NN + 127) / 128), 256>>>(W, bias, out);
}

// round 4
// speedup vs baseline: 1.9974x; 1.2163x over previous
#include <cuda_runtime.h>
#include <cstdint>

#define NN 50000
#define NE 800000
#define F 64
#define KF 256    // F * K
#define OUTF 256

// Scratch (device globals: allocation-free rule)
__device__ int   g_degi[NN];
__device__ int   g_rowptr[NN + 1];
__device__ int   g_cursor[NN];
__device__ int   g_csrc[NE];
__device__ __align__(16) float g_dsqrt[NN];
__device__ __align__(16) float g_scaled_a[NN * F];
__device__ __align__(16) float g_scaled_b[NN * F];
__device__ __align__(16) float g_Xt[(size_t)NN * KF];

__global__ void k_zero() {
    int i = blockIdx.x * blockDim.x + threadIdx.x;
    if (i < NN) g_degi[i] = 0;
}

__global__ void k_deg(const int* __restrict__ dst) {
    int e = blockIdx.x * blockDim.x + threadIdx.x;
    if (e < NE) atomicAdd(&g_degi[dst[e]], 1);
}

// Single-block exclusive scan over 50k degrees -> row_ptr (+ cursor copy).
__global__ __launch_bounds__(1024) void k_scan() {
    __shared__ int sums[1024];
    const int t = threadIdx.x;
    const int CH = (NN + 1023) / 1024;          // 49
    int lo = t * CH, hi = min(lo + CH, NN);
    int s = 0;
    for (int i = lo; i < hi; i++) s += g_degi[i];
    sums[t] = s;
    __syncthreads();
    for (int off = 1; off < 1024; off <<= 1) {
        int v = (t >= off) ? sums[t - off] : 0;
        __syncthreads();
        sums[t] += v;
        __syncthreads();
    }
    int base = (t == 0) ? 0 : sums[t - 1];
    for (int i = lo; i < hi; i++) {
        g_rowptr[i] = base;
        g_cursor[i] = base;
        base += g_degi[i];
    }
    if (t == 1023) g_rowptr[NN] = sums[1023];
}

__global__ void k_fill(const int* __restrict__ src, const int* __restrict__ dst) {
    int e = blockIdx.x * blockDim.x + threadIdx.x;
    if (e < NE) {
        int pos = atomicAdd(&g_cursor[dst[e]], 1);
        g_csrc[pos] = src[e];
    }
}

// One thread per (node, 4-float chunk): d^-1/2, X0, first scaled buffer.
__global__ void k_prep(const float* __restrict__ x) {
    int t = blockIdx.x * blockDim.x + threadIdx.x;
    if (t >= NN * 16) return;
    int i = t >> 4, c = t & 15;
    float ds = rsqrtf((float)max(g_degi[i], 1));
    if (c == 0) g_dsqrt[i] = ds;
    float4 v = ((const float4*)x)[(size_t)i * 16 + c];
    ((float4*)(g_Xt + (size_t)i * KF))[c] = v;   // X0 into block 0
    float4 s = make_float4(v.x * ds, v.y * ds, v.z * ds, v.w * ds);
    ((float4*)g_scaled_a)[(size_t)i * 16 + c] = s;
}

// Gather-based Laplacian + fused Chebyshev recurrence. Ping-pong scaled buffers.
__global__ __launch_bounds__(256) void k_gather_cheb(const float* __restrict__ lambda_max,
                                                     int step, int ping) {
    int t = blockIdx.x * blockDim.x + threadIdx.x;
    if (t >= NN * 16) return;
    int i = t >> 4, c = t & 15;
    const float4* in = (const float4*)(ping ? g_scaled_b : g_scaled_a);
    float4* outb = (float4*)(ping ? g_scaled_a : g_scaled_b);

    int lo = g_rowptr[i], hi = g_rowptr[i + 1];
    float4 a0 = make_float4(0.f, 0.f, 0.f, 0.f);
    float4 a1 = make_float4(0.f, 0.f, 0.f, 0.f);
    int j = lo;
    for (; j + 1 < hi; j += 2) {
        int s0 = __ldg(&g_csrc[j]);
        int s1 = __ldg(&g_csrc[j + 1]);
        float4 v0 = in[(size_t)s0 * 16 + c];
        float4 v1 = in[(size_t)s1 * 16 + c];
        a0.x += v0.x; a0.y += v0.y; a0.z += v0.z; a0.w += v0.w;
        a1.x += v1.x; a1.y += v1.y; a1.z += v1.z; a1.w += v1.w;
    }
    if (j < hi) {
        int s0 = __ldg(&g_csrc[j]);
        float4 v0 = in[(size_t)s0 * 16 + c];
        a0.x += v0.x; a0.y += v0.y; a0.z += v0.z; a0.w += v0.w;
    }
    float ds = g_dsqrt[i];
    float4 L = make_float4((a0.x + a1.x) * ds, (a0.y + a1.y) * ds,
                           (a0.z + a1.z) * ds, (a0.w + a1.w) * ds);

    float rn = 2.0f / lambda_max[0];
    float4* XtRow = (float4*)(g_Xt + (size_t)i * KF);
    float4 xp = XtRow[(step - 1) * 16 + c];
    float4 xn;
    if (step == 1) {
        float cL = -rn, cP = rn - 1.0f;
        xn = make_float4(cL * L.x + cP * xp.x, cL * L.y + cP * xp.y,
                         cL * L.z + cP * xp.z, cL * L.w + cP * xp.w);
    } else {
        float4 xpp = XtRow[(step - 2) * 16 + c];
        float cL = -2.0f * rn, cP = 2.0f * (rn - 1.0f);
        xn = make_float4(cL * L.x + cP * xp.x - xpp.x, cL * L.y + cP * xp.y - xpp.y,
                         cL * L.z + cP * xp.z - xpp.z, cL * L.w + cP * xp.w - xpp.w);
    }
    XtRow[step * 16 + c] = xn;
    outb[(size_t)i * 16 + c] = make_float4(xn.x * ds, xn.y * ds, xn.z * ds, xn.w * ds);
}

// ---------------------------------------------------------------------------
// TF32 tensor-core GEMM: out[50000,256] = relu(Xt[50000,256] @ W[256,256] + b)
// 128x128 block tile, BK=32, 256 threads (8 warps, 4x2), warp tile 32x64,
// mma.sync.m16n8k8.tf32. Smem pitch 36 (== 4 mod 32) => conflict-free frags.
// ---------------------------------------------------------------------------
#define PITCH 36

__device__ __forceinline__ uint32_t f2tf32(float x) {
    uint32_t u;
    asm("cvt.rna.tf32.f32 %0, %1;" : "=r"(u) : "f"(x));
    return u;
}

__global__ __launch_bounds__(256) void k_gemm_tc(const float* __restrict__ W,
                                                 const float* __restrict__ bias,
                                                 float* __restrict__ out) {
    __shared__ uint32_t As[128 * PITCH];
    __shared__ uint32_t Bs[128 * PITCH];   // transposed: Bs[n][k]

    const int tid  = threadIdx.x;
    const int lane = tid & 31;
    const int warp = tid >> 5;
    const int warp_m = warp & 3;   // 0..3  -> 32-row slab
    const int warp_n = warp >> 2;  // 0..1  -> 64-col slab
    const int g = lane >> 2;       // groupID 0..7
    const int t = lane & 3;        // thread-in-group 0..3

    const int m0 = blockIdx.y * 128;
    const int n0 = blockIdx.x * 128;

    const int arow  = tid >> 1;          // 0..127
    const int ahalf = (tid & 1) * 16;    // 0 or 16 within BK
    const int brow  = tid >> 1;          // n index 0..127
    const int khalf = (tid & 1) * 16;

    float c[2][8][4];
    #pragma unroll
    for (int i = 0; i < 2; i++)
        #pragma unroll
        for (int j = 0; j < 8; j++)
            #pragma unroll
            for (int r = 0; r < 4; r++) c[i][j][r] = 0.f;

    const bool arow_ok = (m0 + arow) < NN;
    const float* gA = g_Xt + (size_t)(m0 + arow) * KF + ahalf;

    for (int kk = 0; kk < KF; kk += 32) {
        // ---- load A tile (with bounds + tf32 convert) ----
        #pragma unroll
        for (int j = 0; j < 4; j++) {
            float4 v = arow_ok ? *(const float4*)(gA + kk + j * 4)
                               : make_float4(0.f, 0.f, 0.f, 0.f);
            uint32_t* p = &As[arow * PITCH + ahalf + j * 4];
            p[0] = f2tf32(v.x); p[1] = f2tf32(v.y);
            p[2] = f2tf32(v.z); p[3] = f2tf32(v.w);
        }
        // ---- load B tile transposed (Bs[n][k]) ----
        #pragma unroll
        for (int j = 0; j < 16; j++) {
            float w = W[(size_t)(kk + khalf + j) * OUTF + n0 + brow];
            Bs[brow * PITCH + khalf + j] = f2tf32(w);
        }
        __syncthreads();

        #pragma unroll
        for (int kt = 0; kt < 4; kt++) {
            const int k0 = kt * 8;
            uint32_t a[2][4], b[8][2];
            #pragma unroll
            for (int mt = 0; mt < 2; mt++) {
                int base = warp_m * 32 + mt * 16;
                a[mt][0] = As[(base + g) * PITCH + k0 + t];
                a[mt][1] = As[(base + g + 8) * PITCH + k0 + t];
                a[mt][2] = As[(base + g) * PITCH + k0 + t + 4];
                a[mt][3] = As[(base + g + 8) * PITCH + k0 + t + 4];
            }
            #pragma unroll
            for (int nt = 0; nt < 8; nt++) {
                int nb = warp_n * 64 + nt * 8;
                b[nt][0] = Bs[(nb + g) * PITCH + k0 + t];
                b[nt][1] = Bs[(nb + g) * PITCH + k0 + t + 4];
            }
            #pragma unroll
            for (int mt = 0; mt < 2; mt++)
                #pragma unroll
                for (int nt = 0; nt < 8; nt++) {
                    asm volatile(
                        "mma.sync.aligned.m16n8k8.row.col.f32.tf32.tf32.f32 "
                        "{%0,%1,%2,%3}, {%4,%5,%6,%7}, {%8,%9}, {%0,%1,%2,%3};"
                        : "+f"(c[mt][nt][0]), "+f"(c[mt][nt][1]),
                          "+f"(c[mt][nt][2]), "+f"(c[mt][nt][3])
                        : "r"(a[mt][0]), "r"(a[mt][1]), "r"(a[mt][2]), "r"(a[mt][3]),
                          "r"(b[nt][0]), "r"(b[nt][1]));
                }
        }
        __syncthreads();
    }

    // ---- epilogue: bias + relu ----
    #pragma unroll
    for (int nt = 0; nt < 8; nt++) {
        int col = n0 + warp_n * 64 + nt * 8 + 2 * t;
        float bx = bias[col], by = bias[col + 1];
        #pragma unroll
        for (int mt = 0; mt < 2; mt++) {
            int r0 = m0 + warp_m * 32 + mt * 16 + g;
            if (r0 < NN) {
                float2 v = make_float2(fmaxf(c[mt][nt][0] + bx, 0.f),
                                       fmaxf(c[mt][nt][1] + by, 0.f));
                *(float2*)(out + (size_t)r0 * OUTF + col) = v;
            }
            int r1 = r0 + 8;
            if (r1 < NN) {
                float2 v = make_float2(fmaxf(c[mt][nt][2] + bx, 0.f),
                                       fmaxf(c[mt][nt][3] + by, 0.f));
                *(float2*)(out + (size_t)r1 * OUTF + col) = v;
            }
        }
    }
}

extern "C" void kernel_launch(void* const* d_in, const int* in_sizes, int n_in,
                              void* d_out, int out_size) {
    const float* signal = (const float*)d_in[0];
    const int*   src    = (const int*)d_in[1];
    const int*   dst    = (const int*)d_in[2];
    const float* lam    = (const float*)d_in[3];
    const float* W      = (const float*)d_in[4];
    const float* bias   = (const float*)d_in[5];
    float* out = (float*)d_out;

    k_zero<<<(NN + 255) / 256, 256>>>();
    k_deg<<<(NE + 255) / 256, 256>>>(dst);
    k_scan<<<1, 1024>>>();
    k_fill<<<(NE + 255) / 256, 256>>>(src, dst);
    k_prep<<<(NN * 16 + 255) / 256, 256>>>(signal);

    // step 1: in = a, out = b; step 2: in = b, out = a; step 3: in = a, out = b
    k_gather_cheb<<<(NN * 16 + 255) / 256, 256>>>(lam, 1, 0);
    k_gather_cheb<<<(NN * 16 + 255) / 256, 256>>>(lam, 2, 1);
    k_gather_cheb<<<(NN * 16 + 255) / 256, 256>>>(lam, 3, 0);

    k_gemm_tc<<<dim3(OUTF / 128, (NN + 127) / 128), 256>>>(W, bias, out);
}